// round 2
// baseline (speedup 1.0000x reference)
#include <cuda_runtime.h>
#include <math.h>

#define NN    50000
#define EE    600000
#define DD    128
#define RREL2 474          /* 2R */
#define QQ    128
#define KTOT  1664         /* 13*D */
#define RELSZ (RREL2*DD)   /* 60672 */

// -------- scratch (static device globals; no allocation allowed) --------
__device__ float    g_rel[RELSZ];
__device__ int      g_row_start[NN + 1];
__device__ int      g_cursor[NN];
__device__ unsigned g_packed[EE];                 // src (16b) | attr<<16 (9b)
__device__ float    g_feat4[(size_t)NN * 4 * DD]; // [N, 512] interleaved mean,max,min,std
__device__ float    g_logdeg[NN];
__device__ float    g_logdeg_mean;

// ======================= K1: rel = query @ Wr^T + br =======================
// one warp per output element (coalesced 128B reads of each Wr row)
__global__ void rel_kernel(const float* __restrict__ Wr,
                           const float* __restrict__ br,
                           const float* __restrict__ query) {
    int warp = (blockIdx.x * blockDim.x + threadIdx.x) >> 5;
    int lane = threadIdx.x & 31;
    if (warp >= RELSZ) return;
    const float* w = Wr + (size_t)warp * QQ;
    float s = w[lane]      * __ldg(&query[lane])
            + w[lane + 32] * __ldg(&query[lane + 32])
            + w[lane + 64] * __ldg(&query[lane + 64])
            + w[lane + 96] * __ldg(&query[lane + 96]);
    #pragma unroll
    for (int o = 16; o; o >>= 1) s += __shfl_xor_sync(0xffffffffu, s, o);
    if (lane == 0) g_rel[warp] = s + br[warp];
}

// ============ K2: exclusive scan of (int)degree -> row_start, cursor =========
__global__ void scan_kernel(const float* __restrict__ degout) {
    __shared__ int wsum[32];
    __shared__ int carry;
    int t = threadIdx.x, lane = t & 31, w = t >> 5;
    if (t == 0) carry = 0;
    __syncthreads();
    for (int base = 0; base < NN; base += 1024) {
        int i = base + t;
        int v = (i < NN) ? (int)(degout[i] + 0.5f) : 0;
        int x = v;
        #pragma unroll
        for (int o = 1; o < 32; o <<= 1) {
            int y = __shfl_up_sync(0xffffffffu, x, o);
            if (lane >= o) x += y;
        }
        if (lane == 31) wsum[w] = x;
        __syncthreads();
        if (w == 0) {
            int s = wsum[lane];
            #pragma unroll
            for (int o = 1; o < 32; o <<= 1) {
                int y = __shfl_up_sync(0xffffffffu, s, o);
                if (lane >= o) s += y;
            }
            wsum[lane] = s;
        }
        __syncthreads();
        int excl = x - v + (w ? wsum[w - 1] : 0) + carry;
        if (i < NN) { g_row_start[i] = excl; g_cursor[i] = excl; }
        __syncthreads();
        if (t == 1023) carry = excl + v;
        __syncthreads();
    }
    if (t == 0) g_row_start[NN] = carry;
}

// ================= K3: bucket edges into CSR slots ========================
// NOTE: edge_index / edge_attr are int32 on device (JAX x64 disabled downcasts
// the reference's int64 request to int32).
__global__ void fill_kernel(const int* __restrict__ ei,
                            const int* __restrict__ ea) {
    int e = blockIdx.x * blockDim.x + threadIdx.x;
    if (e >= EE) return;
    int src = ei[e];
    int dst = ei[EE + e];
    int a   = ea[e];
    int pos = atomicAdd(&g_cursor[dst], 1);
    g_packed[pos] = (unsigned)src | ((unsigned)a << 16);
}

// ====== K4: per-node gather reduction (no atomics), fused stats epilogue ======
// one warp per node; lane owns columns {lane, lane+32, lane+64, lane+96}
__global__ void agg_kernel(const float* __restrict__ nf,
                           const float* __restrict__ boundary,
                           const float* __restrict__ degout) {
    int n    = (blockIdx.x * blockDim.x + threadIdx.x) >> 5;
    int lane = threadIdx.x & 31;
    if (n >= NN) return;
    int beg = g_row_start[n], end = g_row_start[n + 1];

    float sum[4], sq[4], mx[4], mn[4];
    #pragma unroll
    for (int i = 0; i < 4; i++) { sum[i] = 0.f; sq[i] = 0.f; mx[i] = -INFINITY; mn[i] = INFINITY; }

    for (int e = beg; e < end; e++) {
        unsigned p = g_packed[e];
        const float* sp = nf    + (size_t)(p & 0xFFFFu) * DD;
        const float* fp = g_rel + (size_t)(p >> 16) * DD;
        #pragma unroll
        for (int i = 0; i < 4; i++) {
            int c = lane + 32 * i;
            float m = sp[c] * fp[c];
            sum[i] += m;
            sq[i]  += m * m;
            mx[i]   = fmaxf(mx[i], m);
            mn[i]   = fminf(mn[i], m);
        }
    }

    float d0  = degout[n];
    float deg = d0 + 1.0f;
    bool  has_edge = (d0 > 0.0f);
    float inv = 1.0f / deg;

    #pragma unroll
    for (int i = 0; i < 4; i++) {
        int c = lane + 32 * i;
        float b = boundary[(size_t)n * DD + c];
        float mean   = (sum[i] + b) * inv;
        float sqmean = (sq[i] + b * b) * inv;
        float vmx = has_edge ? mx[i] : 0.0f;
        float vmn = has_edge ? mn[i] : 0.0f;
        vmx = fmaxf(vmx, b);
        vmn = fminf(vmn, b);
        float sd = sqrtf(fmaxf(sqmean - mean * mean, 1e-6f));
        float4 v = make_float4(mean, vmx, vmn, sd);
        *(float4*)&g_feat4[(size_t)n * 512 + 4 * c] = v;
    }
    if (lane == 0) g_logdeg[n] = logf(deg);
}

// ================= K5: deterministic mean of log(deg) ======================
__global__ void mean_kernel() {
    __shared__ float sh[1024];
    float s = 0.f;
    for (int i = threadIdx.x; i < NN; i += 1024) s += g_logdeg[i];
    sh[threadIdx.x] = s;
    __syncthreads();
    for (int o = 512; o; o >>= 1) {
        if (threadIdx.x < (unsigned)o) sh[threadIdx.x] += sh[threadIdx.x + o];
        __syncthreads();
    }
    if (threadIdx.x == 0) g_logdeg_mean = sh[0] / (float)NN;
}

// ===== K6: fused GEMM: out = relu([nf | feat4 (x) scales] @ Wlin^T + blin) =====
// 128x128 output tile, 256 threads, 8x8 per thread, K expanded on the fly.
__global__ void __launch_bounds__(256)
gemm_kernel(const float* __restrict__ nf,
            const float* __restrict__ Wlin,
            const float* __restrict__ blin,
            float* __restrict__ out) {
    __shared__ float Xs[16][132];
    __shared__ float Ws[16][132];
    __shared__ float sc1[128];
    __shared__ float sc2[128];

    int t  = threadIdx.x;
    int n0 = blockIdx.x * 128;
    int kt = t & 15;      // k within tile
    int r0 = t >> 4;      // 0..15 (row group for loads)
    int tx = t & 15;      // output-col group
    int ty = t >> 4;      // node-row group

    if (t < 128) {
        int n = n0 + t;
        float scale = 0.f;
        if (n < NN) scale = g_logdeg[n] / (g_logdeg_mean + 1e-10f);
        sc1[t] = scale;
        sc2[t] = 1.0f / fmaxf(scale, 0.01f);
    }
    __syncthreads();

    float acc[8][8];
    #pragma unroll
    for (int i = 0; i < 8; i++)
        #pragma unroll
        for (int j = 0; j < 8; j++) acc[i][j] = 0.f;

    for (int k0 = 0; k0 < KTOT; k0 += 16) {
        int c = k0 + kt;
        // load / generate X tile
        #pragma unroll
        for (int r = 0; r < 8; r++) {
            int nl = r0 + r * 16;
            int n  = n0 + nl;
            float v = 0.f;
            if (n < NN) {
                if (c < DD) {
                    v = nf[(size_t)n * DD + c];
                } else {
                    int m = c - DD;
                    int q = m / 3;
                    int s = m - 3 * q;
                    float f = g_feat4[(size_t)n * 512 + q];
                    v = (s == 0) ? f : (s == 1 ? f * sc1[nl] : f * sc2[nl]);
                }
            }
            Xs[kt][nl] = v;
        }
        // load W tile
        #pragma unroll
        for (int r = 0; r < 8; r++) {
            int j = r0 + r * 16;
            Ws[kt][j] = Wlin[(size_t)j * KTOT + c];
        }
        __syncthreads();

        #pragma unroll
        for (int kk = 0; kk < 16; kk++) {
            float4 a0 = *(const float4*)&Xs[kk][ty * 4];
            float4 a1 = *(const float4*)&Xs[kk][ty * 4 + 64];
            float4 b0 = *(const float4*)&Ws[kk][tx * 4];
            float4 b1 = *(const float4*)&Ws[kk][tx * 4 + 64];
            float a[8] = {a0.x, a0.y, a0.z, a0.w, a1.x, a1.y, a1.z, a1.w};
            float b[8] = {b0.x, b0.y, b0.z, b0.w, b1.x, b1.y, b1.z, b1.w};
            #pragma unroll
            for (int i = 0; i < 8; i++)
                #pragma unroll
                for (int j = 0; j < 8; j++)
                    acc[i][j] += a[i] * b[j];
        }
        __syncthreads();
    }

    // epilogue: bias + relu, vectorized stores
    float bl[8];
    #pragma unroll
    for (int jj = 0; jj < 8; jj++) {
        int j = tx * 4 + (jj & 3) + (jj >> 2) * 64;
        bl[jj] = __ldg(&blin[j]);
    }
    #pragma unroll
    for (int i = 0; i < 8; i++) {
        int nl = ty * 4 + (i & 3) + (i >> 2) * 64;
        int n  = n0 + nl;
        if (n >= NN) continue;
        float4 o0, o1;
        o0.x = fmaxf(acc[i][0] + bl[0], 0.f);
        o0.y = fmaxf(acc[i][1] + bl[1], 0.f);
        o0.z = fmaxf(acc[i][2] + bl[2], 0.f);
        o0.w = fmaxf(acc[i][3] + bl[3], 0.f);
        o1.x = fmaxf(acc[i][4] + bl[4], 0.f);
        o1.y = fmaxf(acc[i][5] + bl[5], 0.f);
        o1.z = fmaxf(acc[i][6] + bl[6], 0.f);
        o1.w = fmaxf(acc[i][7] + bl[7], 0.f);
        *(float4*)&out[(size_t)n * DD + tx * 4]      = o0;
        *(float4*)&out[(size_t)n * DD + tx * 4 + 64] = o1;
    }
}

// ============================== launch ====================================
extern "C" void kernel_launch(void* const* d_in, const int* in_sizes, int n_in,
                              void* d_out, int out_size) {
    const float* nf    = (const float*)d_in[0];   // node_features [N,D]
    const float* query = (const float*)d_in[1];   // [1,Q]
    const float* bnd   = (const float*)d_in[2];   // boundary [N,D]
    const float* deg   = (const float*)d_in[3];   // degree_out [N]
    const float* Wr    = (const float*)d_in[4];   // [2R*D, Q]
    const float* br    = (const float*)d_in[5];   // [2R*D]
    const float* Wlin  = (const float*)d_in[6];   // [D, 13D]
    const float* blin  = (const float*)d_in[7];   // [D]
    const int*   ei    = (const int*)d_in[8];     // edge_index [2,E] int32
    const int*   ea    = (const int*)d_in[9];     // edge_attr [E] int32
    float*       out   = (float*)d_out;           // [N,D]

    rel_kernel <<<(RELSZ * 32 + 255) / 256, 256>>>(Wr, br, query);
    scan_kernel<<<1, 1024>>>(deg);
    fill_kernel<<<(EE + 255) / 256, 256>>>(ei, ea);
    agg_kernel <<<(NN * 32 + 255) / 256, 256>>>(nf, bnd, deg);
    mean_kernel<<<1, 1024>>>();
    gemm_kernel<<<(NN + 127) / 128, 256>>>(nf, Wlin, blin, out);
}